// round 10
// baseline (speedup 1.0000x reference)
#include <cuda_runtime.h>
#include <cuda_fp16.h>
#include <cstdint>

// ===========================================================================
// Problem constants
// ===========================================================================
#define BATCH_ 4
#define H_ 16
#define S_ 2048
#define D_ 128
#define NPAT_ 4

static constexpr float QSCALE = (float)(0.08838834764831845 * 1.4426950408889634); // 1/sqrt(128)*log2(e)

static constexpr int BR = 128;        // q rows per CTA
static constexpr int BC = 64;         // kv cols per tile
static constexpr int NT = S_ / BC;    // 32 tiles
static constexpr int NTHREAD = 256;   // 8 warps

// word = uint32 = f16x2
static constexpr int QSTRIDE = 68;    // words per Q row  (64 data + 4 pad)
static constexpr int KSTRIDE = 68;    // words per K row
static constexpr int VSTRIDE = 36;    // words per Vt row (32 data + 4 pad)

static constexpr int Q_TILE_B = BR * QSTRIDE * 4;    // 34816
static constexpr int K_TILE_B = BC * KSTRIDE * 4;    // 17408
static constexpr int V_TILE_B = D_ * VSTRIDE * 4;    // 18432

// smem layout: Q, K x2, V x2, mbars  (106,560 B -> 2 CTAs/SM)
static constexpr int OFF_Q   = 0;                        // 34816
static constexpr int OFF_K   = Q_TILE_B;                 // 34816; 2 x 17408
static constexpr int OFF_V   = OFF_K + 2 * K_TILE_B;     // 69632; 2 x 18432
static constexpr int OFF_CT  = OFF_V + 2 * V_TILE_B;     // 106496
static constexpr int SMEM_BYTES = OFF_CT + 64;           // 106560

// ===========================================================================
// Device scratch (f16x2 words)
// ===========================================================================
__device__ __align__(16) uint32_t g_Qh[(size_t)BATCH_ * H_ * S_ * QSTRIDE];    // padded+permuted rows
__device__ __align__(16) uint32_t g_K [(size_t)BATCH_ * H_ * NT * BC * KSTRIDE];
__device__ __align__(16) uint32_t g_Vt[(size_t)BATCH_ * H_ * NT * D_ * VSTRIDE];
__device__ uint32_t g_maskbits[NPAT_ * S_ * (S_ / 32)];
__device__ int g_pat_idx[H_];

// ===========================================================================
// helpers
// ===========================================================================
__device__ __forceinline__ uint32_t packh2(float lo, float hi) {
    __half2 h = __floats2half2_rn(lo, hi);
    return *(uint32_t*)&h;
}
__device__ __forceinline__ float ex2(float x) {
    float r; asm("ex2.approx.f32 %0, %1;" : "=f"(r) : "f"(x)); return r;
}
__device__ __forceinline__ void mma16(float c[4],
                                      uint32_t a0, uint32_t a1, uint32_t a2, uint32_t a3,
                                      uint32_t b0, uint32_t b1) {
    asm volatile(
        "mma.sync.aligned.m16n8k16.row.col.f32.f16.f16.f32 "
        "{%0,%1,%2,%3}, {%4,%5,%6,%7}, {%8,%9}, {%0,%1,%2,%3};"
        : "+f"(c[0]), "+f"(c[1]), "+f"(c[2]), "+f"(c[3])
        : "r"(a0), "r"(a1), "r"(a2), "r"(a3), "r"(b0), "r"(b1));
}
__device__ __forceinline__ uint32_t smem_u32(const void* p) {
    uint32_t a;
    asm("{ .reg .u64 t; cvta.to.shared.u64 t, %1; cvt.u32.u64 %0, t; }" : "=r"(a) : "l"(p));
    return a;
}
__device__ __forceinline__ void mbar_init(uint32_t m, uint32_t cnt) {
    asm volatile("mbarrier.init.shared.b64 [%0], %1;" :: "r"(m), "r"(cnt) : "memory");
}
__device__ __forceinline__ void mbar_expect(uint32_t m, uint32_t bytes) {
    asm volatile("mbarrier.arrive.expect_tx.shared.b64 _, [%0], %1;" :: "r"(m), "r"(bytes) : "memory");
}
__device__ __forceinline__ void mbar_wait(uint32_t m, uint32_t par) {
    asm volatile(
        "{\n\t.reg .pred P;\n\t"
        "WL_%=:\n\t"
        "mbarrier.try_wait.parity.acquire.cta.shared::cta.b64 P, [%0], %1, 0x989680;\n\t"
        "@P bra.uni WD_%=;\n\t"
        "bra.uni WL_%=;\n\t"
        "WD_%=:\n\t}"
        :: "r"(m), "r"(par) : "memory");
}
__device__ __forceinline__ void bulk_g2s(uint32_t dst, const void* src, uint32_t bytes, uint32_t mbar) {
    asm volatile(
        "cp.async.bulk.shared::cluster.global.mbarrier::complete_tx::bytes [%0], [%1], %2, [%3];"
        :: "r"(dst), "l"(src), "r"(bytes), "r"(mbar) : "memory");
}
// word permutation within 8-word groups: w -> (w&~7) | ((w&3)<<1) | ((w>>2)&1)
__device__ __forceinline__ int permw(int w) {
    return (w & ~7) | (((w & 3) << 1) | ((w >> 2) & 1));
}

// ===========================================================================
// kernel 1: pattern selector MLP
// ===========================================================================
__global__ void selector_kernel(const float* __restrict__ w1, const float* __restrict__ b1,
                                const float* __restrict__ w2, const float* __restrict__ b2) {
    int h = threadIdx.x;
    if (h >= H_) return;
    const float f0 = 1.0f, f1 = (float)h / 12.0f, f2 = 0.5f;
    float logits[NPAT_];
#pragma unroll
    for (int k = 0; k < NPAT_; ++k) logits[k] = b2[k];
    for (int j = 0; j < 32; ++j) {
        float hj = fmaxf(f0 * w1[j] + f1 * w1[32 + j] + f2 * w1[64 + j] + b1[j], 0.0f);
#pragma unroll
        for (int k = 0; k < NPAT_; ++k) logits[k] += hj * w2[j * NPAT_ + k];
    }
    int bi = 0; float bv = logits[0];
#pragma unroll
    for (int k = 1; k < NPAT_; ++k)
        if (logits[k] > bv) { bv = logits[k]; bi = k; }
    g_pat_idx[h] = bi;
}

// ===========================================================================
// kernel 2: bit-pack masks (sigmoid(m)>0.5 <=> m>0)
// ===========================================================================
__global__ void bitpack_kernel(const float* __restrict__ pm) {
    unsigned e = blockIdx.x * 256u + threadIdx.x;
    unsigned w = __ballot_sync(0xffffffffu, pm[e] > 0.0f);
    if ((threadIdx.x & 31) == 0) g_maskbits[e >> 5] = w;
}

// ===========================================================================
// kernel 3: Q -> f16 * (scale*log2e), padded rows of 68 words, word-permuted
// ===========================================================================
__global__ void convert_q(const float* __restrict__ src) {
    size_t e4 = (size_t)blockIdx.x * 256 + threadIdx.x;
    float4 v = ((const float4*)src)[e4];
    size_t row = e4 >> 5;          // 32 float4 per 128-elem row
    int d4 = (int)(e4 & 31);
    uint32_t* dst = g_Qh + row * QSTRIDE;
    int w = d4 * 2;
    dst[permw(w)]     = packh2(v.x * QSCALE, v.y * QSCALE);
    dst[permw(w + 1)] = packh2(v.z * QSCALE, v.w * QSCALE);
}

// ===========================================================================
// kernel 4: K -> f16, tiled [bh][32][64 rows][68 words], word-permuted
// ===========================================================================
__global__ void convert_k(const float* __restrict__ src) {
    size_t e4 = (size_t)blockIdx.x * 256 + threadIdx.x;
    size_t bh = e4 >> 16;
    int rem = (int)(e4 & 65535);
    int s = rem >> 5, d4 = rem & 31;
    int tile = s >> 6, r = s & 63;
    float4 v = ((const float4*)src)[e4];
    uint32_t* dst = g_K + (((size_t)bh * NT + tile) * BC + r) * KSTRIDE;
    int w = d4 * 2;
    dst[permw(w)]     = packh2(v.x, v.y);
    dst[permw(w + 1)] = packh2(v.z, v.w);
}

// ===========================================================================
// kernel 5: V -> Vt f16, tiled [bh][32][128 d][36 words], word-permuted
// ===========================================================================
__global__ void transpose_v(const float* __restrict__ V) {
    __shared__ float ts[32][33];   // [t-local][d-local]
    int bh = blockIdx.z;
    int t0 = blockIdx.y * 32;
    int d0 = blockIdx.x * 32;
    const float* src = V + ((size_t)bh * S_ + t0) * D_ + d0;
    int tx = threadIdx.x, ty = threadIdx.y;
#pragma unroll
    for (int i = 0; i < 4; ++i)
        ts[ty + i * 8][tx] = src[(size_t)(ty + i * 8) * D_ + tx];
    __syncthreads();
    int tile = t0 >> 6;
    int tbase = (t0 & 63) >> 1;          // word base within row: 0 or 16
    uint32_t* dst = g_Vt + ((size_t)bh * NT + tile) * (size_t)D_ * VSTRIDE;
    int l = ty * 32 + tx;
#pragma unroll
    for (int i = 0; i < 2; ++i) {
        int dl = (l >> 4) + i * 16;      // d-local 0..31
        int j  = l & 15;                 // t-pair within slab
        uint32_t val = packh2(ts[2 * j][dl], ts[2 * j + 1][dl]);
        dst[(size_t)(d0 + dl) * VSTRIDE + permw(tbase + j)] = val;
    }
}

// ===========================================================================
// kernel 6: flash attention — fp16 mma, P in registers (C->A frag reuse),
//           Q in smem, 2 CTAs/SM, one __syncthreads per KV tile
// ===========================================================================
__global__ void __launch_bounds__(NTHREAD, 2)
attn_kernel(float* __restrict__ O) {
    extern __shared__ unsigned char smraw[];
    const uint32_t sbase = smem_u32(smraw);

    const int tid  = threadIdx.x;
    const int wid  = tid >> 5;
    const int lane = tid & 31;
    const int g    = lane >> 2;
    const int tg   = lane & 3;

    const int qt = blockIdx.x, h = blockIdx.y, b = blockIdx.z;
    const int bh = b * H_ + h;
    const int q0 = qt * BR;

    // warp rows (m16): ra (g block) and rb (+8)
    const int ra = wid * 16 + g;
    const int rb = ra + 8;

    uint32_t kbar[2], vbar[2], qbar;
    kbar[0] = sbase + OFF_CT;      kbar[1] = sbase + OFF_CT + 8;
    vbar[0] = sbase + OFF_CT + 16; vbar[1] = sbase + OFF_CT + 24;
    qbar    = sbase + OFF_CT + 32;

    const uint32_t* Qrows  = g_Qh + (size_t)(bh * S_ + q0) * QSTRIDE;
    const uint32_t* Ktiles = g_K  + (size_t)bh * NT * BC * KSTRIDE;
    const uint32_t* Vtiles = g_Vt + (size_t)bh * NT * D_ * VSTRIDE;
    if (tid == 0) {
        mbar_init(qbar, 1);
#pragma unroll
        for (int i = 0; i < 2; ++i) { mbar_init(kbar[i], 1); mbar_init(vbar[i], 1); }
        mbar_expect(qbar, Q_TILE_B);
        bulk_g2s(sbase + OFF_Q, Qrows, Q_TILE_B, qbar);
#pragma unroll
        for (int i = 0; i < 2; ++i) {
            mbar_expect(kbar[i], K_TILE_B);
            bulk_g2s(sbase + OFF_K + i * K_TILE_B, Ktiles + (size_t)i * BC * KSTRIDE, K_TILE_B, kbar[i]);
            mbar_expect(vbar[i], V_TILE_B);
            bulk_g2s(sbase + OFF_V + i * V_TILE_B, Vtiles + (size_t)i * D_ * VSTRIDE, V_TILE_B, vbar[i]);
        }
    }

    const int pat = g_pat_idx[h];
    const uint32_t* mrow0 = g_maskbits + ((size_t)pat * S_ + q0 + ra) * (S_ / 32);
    const uint32_t* mrow1 = g_maskbits + ((size_t)pat * S_ + q0 + rb) * (S_ / 32);

    float oacc[16][4];
#pragma unroll
    for (int i = 0; i < 16; ++i) { oacc[i][0] = oacc[i][1] = oacc[i][2] = oacc[i][3] = 0.f; }
    float l0 = 0.f, l1 = 0.f;

    const uint32_t* Qs = (const uint32_t*)(smraw + OFF_Q);
    __syncthreads();            // mbarrier init visible
    mbar_wait(qbar, 0);         // Q tile resident

    for (int jt = 0; jt < NT; ++jt) {
        const int bi = jt & 1;
        const int par = (jt >> 1) & 1;

        // ---- S(jt) = Q K^T  (warp: 16 x 64) ----
        mbar_wait(kbar[bi], par);
        const uint32_t* Ksm = (const uint32_t*)(smraw + OFF_K + bi * K_TILE_B);
        float sacc[8][4];
#pragma unroll
        for (int i = 0; i < 8; ++i) { sacc[i][0] = sacc[i][1] = sacc[i][2] = sacc[i][3] = 0.f; }
#pragma unroll
        for (int kk = 0; kk < 8; ++kk) {
            uint2 a = *(const uint2*)(Qs + ra * QSTRIDE + kk * 8 + 2 * tg);  // (a0, a2)
            uint2 c = *(const uint2*)(Qs + rb * QSTRIDE + kk * 8 + 2 * tg);  // (a1, a3)
#pragma unroll
            for (int nt = 0; nt < 8; ++nt) {
                uint2 bb = *(const uint2*)(Ksm + (nt * 8 + g) * KSTRIDE + kk * 8 + 2 * tg);
                mma16(sacc[nt], a.x, c.x, a.y, c.y, bb.x, bb.y);
            }
        }

        // ---- mask + exp2 -> P A-fragments in registers (C->A layout identity) ----
        const uint32_t w00 = __ldg(mrow0 + 2 * jt);
        const uint32_t w01 = __ldg(mrow0 + 2 * jt + 1);
        const uint32_t w10 = __ldg(mrow1 + 2 * jt);
        const uint32_t w11 = __ldg(mrow1 + 2 * jt + 1);
        uint32_t pa0[4], pa1[4], pa2[4], pa3[4];   // [u] = k-group (16 t each)
#pragma unroll
        for (int u = 0; u < 4; ++u) {
            const uint32_t wa = (u < 2) ? w00 : w01;
            const uint32_t wb = (u < 2) ? w10 : w11;
            const int c0 = (16 * u + 2 * tg) & 31;       // bit for sacc[2u]
            const int c1 = c0 + 8;                       // bit for sacc[2u+1]
            float p00 = ((wa >> c0) & 1u)       ? ex2(sacc[2 * u][0]) : 1.0f;
            float p01 = ((wa >> (c0 + 1)) & 1u) ? ex2(sacc[2 * u][1]) : 1.0f;
            float p10 = ((wb >> c0) & 1u)       ? ex2(sacc[2 * u][2]) : 1.0f;
            float p11 = ((wb >> (c0 + 1)) & 1u) ? ex2(sacc[2 * u][3]) : 1.0f;
            float q00 = ((wa >> c1) & 1u)       ? ex2(sacc[2 * u + 1][0]) : 1.0f;
            float q01 = ((wa >> (c1 + 1)) & 1u) ? ex2(sacc[2 * u + 1][1]) : 1.0f;
            float q10 = ((wb >> c1) & 1u)       ? ex2(sacc[2 * u + 1][2]) : 1.0f;
            float q11 = ((wb >> (c1 + 1)) & 1u) ? ex2(sacc[2 * u + 1][3]) : 1.0f;
            l0 += (p00 + p01) + (q00 + q01);
            l1 += (p10 + p11) + (q10 + q11);
            pa0[u] = packh2(p00, p01);   // row ra, k lo
            pa1[u] = packh2(p10, p11);   // row rb, k lo
            pa2[u] = packh2(q00, q01);   // row ra, k hi
            pa3[u] = packh2(q10, q11);   // row rb, k hi
        }

        // ---- O += P Vt  (warp: 16 x 128, k = 64) ----
        mbar_wait(vbar[bi], par);
        const uint32_t* Vsm = (const uint32_t*)(smraw + OFF_V + bi * V_TILE_B);
#pragma unroll
        for (int u = 0; u < 4; ++u) {
#pragma unroll
            for (int nt = 0; nt < 16; ++nt) {
                uint2 bb = *(const uint2*)(Vsm + (nt * 8 + g) * VSTRIDE + u * 8 + 2 * tg);
                mma16(oacc[nt], pa0[u], pa1[u], pa2[u], pa3[u], bb.x, bb.y);
            }
        }
        __syncthreads();   // all warps done with K(jt)/V(jt) — buffers reusable

        // ---- prefetch tile jt+2 into buffer bi ----
        if (tid == 0 && jt + 2 < NT) {
            mbar_expect(kbar[bi], K_TILE_B);
            bulk_g2s(sbase + OFF_K + bi * K_TILE_B, Ktiles + (size_t)(jt + 2) * BC * KSTRIDE, K_TILE_B, kbar[bi]);
            mbar_expect(vbar[bi], V_TILE_B);
            bulk_g2s(sbase + OFF_V + bi * V_TILE_B, Vtiles + (size_t)(jt + 2) * D_ * VSTRIDE, V_TILE_B, vbar[bi]);
        }
    }

    // ---- l reduce (warp-local rows) + epilogue ----
    l0 += __shfl_xor_sync(0xffffffffu, l0, 1);
    l0 += __shfl_xor_sync(0xffffffffu, l0, 2);
    l1 += __shfl_xor_sync(0xffffffffu, l1, 1);
    l1 += __shfl_xor_sync(0xffffffffu, l1, 2);
    const float inv0 = 1.0f / l0;
    const float inv1 = 1.0f / l1;
    float* O0 = O + ((size_t)bh * S_ + q0 + ra) * D_;
    float* O1 = O + ((size_t)bh * S_ + q0 + rb) * D_;
#pragma unroll
    for (int nt = 0; nt < 16; ++nt) {
        const int c = nt * 8 + tg * 2;
        *(float2*)(O0 + c) = make_float2(oacc[nt][0] * inv0, oacc[nt][1] * inv0);
        *(float2*)(O1 + c) = make_float2(oacc[nt][2] * inv1, oacc[nt][3] * inv1);
    }
}

// ===========================================================================
// launch
// ===========================================================================
extern "C" void kernel_launch(void* const* d_in, const int* in_sizes, int n_in,
                              void* d_out, int out_size) {
    const float* Q  = (const float*)d_in[0];
    const float* K  = (const float*)d_in[1];
    const float* V  = (const float*)d_in[2];
    const float* pm = (const float*)d_in[3];
    const float* w1 = (const float*)d_in[4];
    const float* b1 = (const float*)d_in[5];
    const float* w2 = (const float*)d_in[6];
    const float* b2 = (const float*)d_in[7];
    float* O = (float*)d_out;

    cudaFuncSetAttribute(attn_kernel, cudaFuncAttributeMaxDynamicSharedMemorySize, SMEM_BYTES);

    selector_kernel<<<1, 32>>>(w1, b1, w2, b2);
    bitpack_kernel<<<(NPAT_ * S_ * S_) / 256, 256>>>(pm);
    convert_q<<<16384, 256>>>(Q);
    convert_k<<<16384, 256>>>(K);
    transpose_v<<<dim3(4, 64, 64), dim3(32, 8)>>>(V);
    attn_kernel<<<dim3(S_ / BR, H_, BATCH_), NTHREAD, SMEM_BYTES>>>(O);
}

// round 17
// speedup vs baseline: 1.0908x; 1.0908x over previous
#include <cuda_runtime.h>
#include <cuda_fp16.h>
#include <cstdint>

// ===========================================================================
// Problem constants
// ===========================================================================
#define BATCH_ 4
#define H_ 16
#define S_ 2048
#define D_ 128
#define NPAT_ 4

static constexpr float QSCALE = (float)(0.08838834764831845 * 1.4426950408889634); // 1/sqrt(128)*log2(e)

static constexpr int BR = 128;        // q rows per CTA
static constexpr int BC = 64;         // kv cols per tile
static constexpr int NT = S_ / BC;    // 32 tiles
static constexpr int NTHREAD = 256;   // 8 warps

// word = uint32 = f16x2
static constexpr int KSTRIDE = 68;    // words per K row  (64 data + 4 pad)
static constexpr int VSTRIDE = 36;    // words per Vt row (32 data + 4 pad)
static constexpr int PSTRIDE = 36;

static constexpr int K_TILE_B = BC * KSTRIDE * 4;    // 17408
static constexpr int V_TILE_B = D_ * VSTRIDE * 4;    // 18432

// smem layout: K x3, V x2, P, lrow, mbars
static constexpr int OFF_K   = 0;                       // 3 * 17408 = 52224
static constexpr int OFF_V   = 3 * K_TILE_B;            // 52224; 2 * 18432 = 36864
static constexpr int OFF_P   = OFF_V + 2 * V_TILE_B;    // 89088
static constexpr int OFF_L   = OFF_P + BR * PSTRIDE * 4;// 107520 (+512)
static constexpr int OFF_CT  = OFF_L + 512;             // 108032
static constexpr int SMEM_BYTES = OFF_CT + 64;          // 108096

// ===========================================================================
// Device scratch (f16x2 words)
// ===========================================================================
__device__ __align__(16) uint32_t g_Qh[(size_t)BATCH_ * H_ * S_ * (D_ / 2)];   // PLAIN row-major (R6 layout)
__device__ __align__(16) uint32_t g_K [(size_t)BATCH_ * H_ * NT * BC * KSTRIDE];
__device__ __align__(16) uint32_t g_Vt[(size_t)BATCH_ * H_ * NT * D_ * VSTRIDE];
__device__ uint32_t g_maskbits[NPAT_ * S_ * (S_ / 32)];
__device__ int g_pat_idx[H_];

// ===========================================================================
// helpers
// ===========================================================================
__device__ __forceinline__ uint32_t packh2(float lo, float hi) {
    __half2 h = __floats2half2_rn(lo, hi);
    return *(uint32_t*)&h;
}
__device__ __forceinline__ float ex2(float x) {
    float r; asm("ex2.approx.f32 %0, %1;" : "=f"(r) : "f"(x)); return r;
}
__device__ __forceinline__ void mma16(float c[4],
                                      uint32_t a0, uint32_t a1, uint32_t a2, uint32_t a3,
                                      uint32_t b0, uint32_t b1) {
    asm volatile(
        "mma.sync.aligned.m16n8k16.row.col.f32.f16.f16.f32 "
        "{%0,%1,%2,%3}, {%4,%5,%6,%7}, {%8,%9}, {%0,%1,%2,%3};"
        : "+f"(c[0]), "+f"(c[1]), "+f"(c[2]), "+f"(c[3])
        : "r"(a0), "r"(a1), "r"(a2), "r"(a3), "r"(b0), "r"(b1));
}
__device__ __forceinline__ uint32_t smem_u32(const void* p) {
    uint32_t a;
    asm("{ .reg .u64 t; cvta.to.shared.u64 t, %1; cvt.u32.u64 %0, t; }" : "=r"(a) : "l"(p));
    return a;
}
__device__ __forceinline__ void mbar_init(uint32_t m, uint32_t cnt) {
    asm volatile("mbarrier.init.shared.b64 [%0], %1;" :: "r"(m), "r"(cnt) : "memory");
}
__device__ __forceinline__ void mbar_expect(uint32_t m, uint32_t bytes) {
    asm volatile("mbarrier.arrive.expect_tx.shared.b64 _, [%0], %1;" :: "r"(m), "r"(bytes) : "memory");
}
__device__ __forceinline__ void mbar_wait(uint32_t m, uint32_t par) {
    asm volatile(
        "{\n\t.reg .pred P;\n\t"
        "WL_%=:\n\t"
        "mbarrier.try_wait.parity.acquire.cta.shared::cta.b64 P, [%0], %1, 0x989680;\n\t"
        "@P bra.uni WD_%=;\n\t"
        "bra.uni WL_%=;\n\t"
        "WD_%=:\n\t}"
        :: "r"(m), "r"(par) : "memory");
}
__device__ __forceinline__ void bulk_g2s(uint32_t dst, const void* src, uint32_t bytes, uint32_t mbar) {
    asm volatile(
        "cp.async.bulk.shared::cluster.global.mbarrier::complete_tx::bytes [%0], [%1], %2, [%3];"
        :: "r"(dst), "l"(src), "r"(bytes), "r"(mbar) : "memory");
}
// word permutation within 8-word groups: w -> (w&~7) | ((w&3)<<1) | ((w>>2)&1)
__device__ __forceinline__ int permw(int w) {
    return (w & ~7) | (((w & 3) << 1) | ((w >> 2) & 1));
}

// ===========================================================================
// fused prepass: one launch, blocks partitioned by region
//   block 0                    : selector MLP
//   [1, 1+65536)               : bitpack masks
//   [+0, +16384)               : convert Q (PLAIN layout — matches attn reader)
//   [+0, +16384)               : convert K (permuted tiles)
//   [+0, +16384)               : transpose V (permuted tiles)
// ===========================================================================
static constexpr unsigned NB_BITPACK = (NPAT_ * S_ * S_) / 256;           // 65536
static constexpr unsigned NB_CONV    = 16384;
static constexpr unsigned NB_TOTAL   = 1 + NB_BITPACK + 3 * NB_CONV;      // 114689

__global__ void __launch_bounds__(256)
prepass_kernel(const float* __restrict__ Q, const float* __restrict__ K,
               const float* __restrict__ V, const float* __restrict__ pm,
               const float* __restrict__ w1, const float* __restrict__ b1,
               const float* __restrict__ w2, const float* __restrict__ b2) {
    __shared__ float ts[32][33];
    const int tid = threadIdx.x;
    unsigned bidx = blockIdx.x;

    if (bidx == 0) {
        // ---- selector MLP ----
        int h = tid;
        if (h >= H_) return;
        const float f0 = 1.0f, f1 = (float)h / 12.0f, f2 = 0.5f;
        float logits[NPAT_];
#pragma unroll
        for (int k = 0; k < NPAT_; ++k) logits[k] = b2[k];
        for (int j = 0; j < 32; ++j) {
            float hj = fmaxf(f0 * w1[j] + f1 * w1[32 + j] + f2 * w1[64 + j] + b1[j], 0.0f);
#pragma unroll
            for (int k = 0; k < NPAT_; ++k) logits[k] += hj * w2[j * NPAT_ + k];
        }
        int bi = 0; float bv = logits[0];
#pragma unroll
        for (int k = 1; k < NPAT_; ++k)
            if (logits[k] > bv) { bv = logits[k]; bi = k; }
        g_pat_idx[h] = bi;
        return;
    }
    bidx -= 1;

    if (bidx < NB_BITPACK) {
        // ---- bitpack masks (sigmoid(m)>0.5 <=> m>0) ----
        unsigned e = bidx * 256u + tid;
        unsigned w = __ballot_sync(0xffffffffu, pm[e] > 0.0f);
        if ((tid & 31) == 0) g_maskbits[e >> 5] = w;
        return;
    }
    bidx -= NB_BITPACK;

    if (bidx < NB_CONV) {
        // ---- Q -> f16 * (scale*log2e), PLAIN row-major f16x2 words (R6) ----
        size_t e4 = (size_t)bidx * 256 + tid;
        float4 v = ((const float4*)Q)[e4];
        ((uint2*)g_Qh)[e4] = make_uint2(packh2(v.x * QSCALE, v.y * QSCALE),
                                        packh2(v.z * QSCALE, v.w * QSCALE));
        return;
    }
    bidx -= NB_CONV;

    if (bidx < NB_CONV) {
        // ---- K -> f16, tiled [bh][32][64 rows][68 words], word-permuted ----
        size_t e4 = (size_t)bidx * 256 + tid;
        size_t bh = e4 >> 16;
        int rem = (int)(e4 & 65535);
        int s = rem >> 5, d4 = rem & 31;
        int tile = s >> 6, r = s & 63;
        float4 v = ((const float4*)K)[e4];
        uint32_t* dst = g_K + (((size_t)bh * NT + tile) * BC + r) * KSTRIDE;
        int w = d4 * 2;
        dst[permw(w)]     = packh2(v.x, v.y);
        dst[permw(w + 1)] = packh2(v.z, v.w);
        return;
    }
    bidx -= NB_CONV;

    {
        // ---- V -> Vt f16, tiled [bh][32][128 d][36 words], word-permuted ----
        int d0 = (int)(bidx & 3) * 32;
        int t0 = (int)((bidx >> 2) & 63) * 32;
        int bh = (int)(bidx >> 8);
        const float* src = V + ((size_t)bh * S_ + t0) * D_ + d0;
        int tx = tid & 31, ty = tid >> 5;
#pragma unroll
        for (int i = 0; i < 4; ++i)
            ts[ty + i * 8][tx] = src[(size_t)(ty + i * 8) * D_ + tx];
        __syncthreads();
        int tile = t0 >> 6;
        int tbase = (t0 & 63) >> 1;
        uint32_t* dst = g_Vt + ((size_t)bh * NT + tile) * (size_t)D_ * VSTRIDE;
        int l = tid;
#pragma unroll
        for (int i = 0; i < 2; ++i) {
            int dl = (l >> 4) + i * 16;
            int j  = l & 15;
            uint32_t val = packh2(ts[2 * j][dl], ts[2 * j + 1][dl]);
            dst[(size_t)(d0 + dl) * VSTRIDE + permw(tbase + j)] = val;
        }
    }
}

// ===========================================================================
// attn kernel — EXACT R6 structure (best measured: 729us):
// fp16 mma, K triple-buffer / V double-buffer,
// S(jt+1) interleaved with O(jt), O-phase split m=32 x n=64
// ===========================================================================
__global__ void __launch_bounds__(NTHREAD, 1)
attn_kernel(float* __restrict__ O) {
    extern __shared__ unsigned char smraw[];
    const uint32_t sbase = smem_u32(smraw);

    const int tid  = threadIdx.x;
    const int wid  = tid >> 5;
    const int lane = tid & 31;
    const int g    = lane >> 2;
    const int tg   = lane & 3;

    const int qt = blockIdx.x, h = blockIdx.y, b = blockIdx.z;
    const int bh = b * H_ + h;
    const int q0 = qt * BR;

    // S/softmax mapping: warp handles rows ra, rb (m16)
    const int ra = wid * 16 + g;
    const int rb = ra + 8;
    // O mapping: warp handles rows ro..ro+31, cols co..co+63
    const int ro = (wid & 3) * 32;
    const int co = (wid >> 2) * 64;

    uint32_t kbar[3], vbar[2];
    kbar[0] = sbase + OFF_CT;      kbar[1] = sbase + OFF_CT + 8;  kbar[2] = sbase + OFF_CT + 16;
    vbar[0] = sbase + OFF_CT + 24; vbar[1] = sbase + OFF_CT + 32;

    const uint32_t* Ktiles = g_K  + (size_t)bh * NT * BC * KSTRIDE;
    const uint32_t* Vtiles = g_Vt + (size_t)bh * NT * D_ * VSTRIDE;
    if (tid == 0) {
#pragma unroll
        for (int i = 0; i < 3; ++i) mbar_init(kbar[i], 1);
#pragma unroll
        for (int i = 0; i < 2; ++i) mbar_init(vbar[i], 1);
#pragma unroll
        for (int i = 0; i < 3; ++i) {
            mbar_expect(kbar[i], K_TILE_B);
            bulk_g2s(sbase + OFF_K + i * K_TILE_B, Ktiles + (size_t)i * BC * KSTRIDE, K_TILE_B, kbar[i]);
        }
#pragma unroll
        for (int i = 0; i < 2; ++i) {
            mbar_expect(vbar[i], V_TILE_B);
            bulk_g2s(sbase + OFF_V + i * V_TILE_B, Vtiles + (size_t)i * D_ * VSTRIDE, V_TILE_B, vbar[i]);
        }
    }

    // Q fragments -> registers (8 kgroups x 4 regs) — PLAIN layout
    uint32_t qa0[8], qa1[8], qa2[8], qa3[8];
    {
        const uint32_t* QA = g_Qh + ((size_t)bh * S_ + q0 + ra) * (D_ / 2);
        const uint32_t* QB = g_Qh + ((size_t)bh * S_ + q0 + rb) * (D_ / 2);
#pragma unroll
        for (int kk = 0; kk < 8; ++kk) {
            qa0[kk] = __ldg(QA + kk * 8 + tg);
            qa1[kk] = __ldg(QB + kk * 8 + tg);
            qa2[kk] = __ldg(QA + kk * 8 + tg + 4);
            qa3[kk] = __ldg(QB + kk * 8 + tg + 4);
        }
    }

    const int pat = g_pat_idx[h];
    const uint32_t* mrow0 = g_maskbits + ((size_t)pat * S_ + q0 + ra) * (S_ / 32);
    const uint32_t* mrow1 = g_maskbits + ((size_t)pat * S_ + q0 + rb) * (S_ / 32);

    float oacc[2][8][4];
#pragma unroll
    for (int m = 0; m < 2; ++m)
#pragma unroll
        for (int i = 0; i < 8; ++i) { oacc[m][i][0] = oacc[m][i][1] = oacc[m][i][2] = oacc[m][i][3] = 0.f; }
    float l0 = 0.f, l1 = 0.f;
    float sacc[8][4];

    uint32_t* Ps   = (uint32_t*)(smraw + OFF_P);
    float*    lrow = (float*)(smraw + OFF_L);
    __syncthreads();   // mbarrier init visible

    // ---- S(0) ----
    mbar_wait(kbar[0], 0);
    {
        const uint32_t* Ksm = (const uint32_t*)(smraw + OFF_K);
#pragma unroll
        for (int i = 0; i < 8; ++i) { sacc[i][0] = sacc[i][1] = sacc[i][2] = sacc[i][3] = 0.f; }
#pragma unroll
        for (int kk = 0; kk < 8; ++kk)
#pragma unroll
            for (int nt = 0; nt < 8; ++nt) {
                uint2 bb = *(const uint2*)(Ksm + (nt * 8 + g) * KSTRIDE + kk * 8 + 2 * tg);
                mma16(sacc[nt], qa0[kk], qa1[kk], qa2[kk], qa3[kk], bb.x, bb.y);
            }
    }

    for (int jt = 0; jt < NT; ++jt) {
        // ---- softmax(jt): mask + exp2 + paired P store + per-thread l partial ----
        const uint32_t w00 = __ldg(mrow0 + 2 * jt);
        const uint32_t w01 = __ldg(mrow0 + 2 * jt + 1);
        const uint32_t w10 = __ldg(mrow1 + 2 * jt);
        const uint32_t w11 = __ldg(mrow1 + 2 * jt + 1);
#pragma unroll
        for (int np = 0; np < 4; ++np) {
            const uint32_t wa = (np < 2) ? w00 : w01;
            const uint32_t wb = (np < 2) ? w10 : w11;
            const int c0 = (16 * np + 2 * tg) & 31;      // bit for nt=2np
            const int c1 = c0 + 8;                       // bit for nt=2np+1
            float p00 = ((wa >> c0) & 1u)       ? ex2(sacc[2 * np][0]) : 1.0f;
            float p01 = ((wa >> (c0 + 1)) & 1u) ? ex2(sacc[2 * np][1]) : 1.0f;
            float p10 = ((wb >> c0) & 1u)       ? ex2(sacc[2 * np][2]) : 1.0f;
            float p11 = ((wb >> (c0 + 1)) & 1u) ? ex2(sacc[2 * np][3]) : 1.0f;
            float q00 = ((wa >> c1) & 1u)       ? ex2(sacc[2 * np + 1][0]) : 1.0f;
            float q01 = ((wa >> (c1 + 1)) & 1u) ? ex2(sacc[2 * np + 1][1]) : 1.0f;
            float q10 = ((wb >> c1) & 1u)       ? ex2(sacc[2 * np + 1][2]) : 1.0f;
            float q11 = ((wb >> (c1 + 1)) & 1u) ? ex2(sacc[2 * np + 1][3]) : 1.0f;
            l0 += (p00 + p01) + (q00 + q01);
            l1 += (p10 + p11) + (q10 + q11);
            *(uint2*)(Ps + ra * PSTRIDE + np * 8 + 2 * tg) = make_uint2(packh2(p00, p01), packh2(q00, q01));
            *(uint2*)(Ps + rb * PSTRIDE + np * 8 + 2 * tg) = make_uint2(packh2(p10, p11), packh2(q10, q11));
        }
        __syncthreads();   // P(jt) visible to all warps

        const uint32_t* Vsm = (const uint32_t*)(smraw + OFF_V + (jt & 1) * V_TILE_B);
        mbar_wait(vbar[jt & 1], (jt >> 1) & 1);

        if (jt + 1 < NT) {
            // wait K(jt+1), then interleave S(jt+1) with O(jt)
            const int kb = (jt + 1) % 3;
            mbar_wait(kbar[kb], (((jt + 1) / 3) & 1));
            const uint32_t* Ksm = (const uint32_t*)(smraw + OFF_K + kb * K_TILE_B);
#pragma unroll
            for (int i = 0; i < 8; ++i) { sacc[i][0] = sacc[i][1] = sacc[i][2] = sacc[i][3] = 0.f; }
#pragma unroll
            for (int u = 0; u < 4; ++u) {
                // S part: kgroups 2u, 2u+1
#pragma unroll
                for (int kk = 2 * u; kk < 2 * u + 2; ++kk)
#pragma unroll
                    for (int nt = 0; nt < 8; ++nt) {
                        uint2 bb = *(const uint2*)(Ksm + (nt * 8 + g) * KSTRIDE + kk * 8 + 2 * tg);
                        mma16(sacc[nt], qa0[kk], qa1[kk], qa2[kk], qa3[kk], bb.x, bb.y);
                    }
                // O part: kk = u
#pragma unroll
                for (int mb = 0; mb < 2; ++mb) {
                    uint2 ua = *(const uint2*)(Ps + (ro + 16 * mb + g) * PSTRIDE + u * 8 + 2 * tg);
                    uint2 ub = *(const uint2*)(Ps + (ro + 16 * mb + 8 + g) * PSTRIDE + u * 8 + 2 * tg);
#pragma unroll
                    for (int nt = 0; nt < 8; ++nt) {
                        uint2 bb = *(const uint2*)(Vsm + (co + nt * 8 + g) * VSTRIDE + u * 8 + 2 * tg);
                        mma16(oacc[mb][nt], ua.x, ub.x, ua.y, ub.y, bb.x, bb.y);
                    }
                }
            }
        } else {
            // last tile: O only
#pragma unroll
            for (int u = 0; u < 4; ++u)
#pragma unroll
                for (int mb = 0; mb < 2; ++mb) {
                    uint2 ua = *(const uint2*)(Ps + (ro + 16 * mb + g) * PSTRIDE + u * 8 + 2 * tg);
                    uint2 ub = *(const uint2*)(Ps + (ro + 16 * mb + 8 + g) * PSTRIDE + u * 8 + 2 * tg);
#pragma unroll
                    for (int nt = 0; nt < 8; ++nt) {
                        uint2 bb = *(const uint2*)(Vsm + (co + nt * 8 + g) * VSTRIDE + u * 8 + 2 * tg);
                        mma16(oacc[mb][nt], ua.x, ub.x, ua.y, ub.y, bb.x, bb.y);
                    }
                }
        }
        __syncthreads();   // P(jt)/V(jt)/K(jt+1) reads done

        if (tid == 0) {
            if (jt + 3 < NT) {
                const int kb = jt % 3;
                mbar_expect(kbar[kb], K_TILE_B);
                bulk_g2s(sbase + OFF_K + kb * K_TILE_B, Ktiles + (size_t)(jt + 3) * BC * KSTRIDE, K_TILE_B, kbar[kb]);
            }
            if (jt + 2 < NT) {
                const int vb = jt & 1;
                mbar_expect(vbar[vb], V_TILE_B);
                bulk_g2s(sbase + OFF_V + vb * V_TILE_B, Vtiles + (size_t)(jt + 2) * D_ * VSTRIDE, V_TILE_B, vbar[vb]);
            }
        }
    }

    // ---- l reduce to smem ----
    l0 += __shfl_xor_sync(0xffffffffu, l0, 1);
    l0 += __shfl_xor_sync(0xffffffffu, l0, 2);
    l1 += __shfl_xor_sync(0xffffffffu, l1, 1);
    l1 += __shfl_xor_sync(0xffffffffu, l1, 2);
    if (tg == 0) { lrow[ra] = l0; lrow[rb] = l1; }
    __syncthreads();

    // ---- epilogue (O-split mapping) ----
#pragma unroll
    for (int mb = 0; mb < 2; ++mb) {
        const int r0 = ro + 16 * mb + g;
        const int r1 = r0 + 8;
        const float inv0 = 1.0f / lrow[r0];
        const float inv1 = 1.0f / lrow[r1];
        float* O0 = O + ((size_t)bh * S_ + q0 + r0) * D_ + co;
        float* O1 = O + ((size_t)bh * S_ + q0 + r1) * D_ + co;
#pragma unroll
        for (int nt = 0; nt < 8; ++nt) {
            const int c = nt * 8 + tg * 2;
            *(float2*)(O0 + c) = make_float2(oacc[mb][nt][0] * inv0, oacc[mb][nt][1] * inv0);
            *(float2*)(O1 + c) = make_float2(oacc[mb][nt][2] * inv1, oacc[mb][nt][3] * inv1);
        }
    }
}

// ===========================================================================
// launch
// ===========================================================================
extern "C" void kernel_launch(void* const* d_in, const int* in_sizes, int n_in,
                              void* d_out, int out_size) {
    const float* Q  = (const float*)d_in[0];
    const float* K  = (const float*)d_in[1];
    const float* V  = (const float*)d_in[2];
    const float* pm = (const float*)d_in[3];
    const float* w1 = (const float*)d_in[4];
    const float* b1 = (const float*)d_in[5];
    const float* w2 = (const float*)d_in[6];
    const float* b2 = (const float*)d_in[7];
    float* O = (float*)d_out;

    cudaFuncSetAttribute(attn_kernel, cudaFuncAttributeMaxDynamicSharedMemorySize, SMEM_BYTES);

    prepass_kernel<<<NB_TOTAL, 256>>>(Q, K, V, pm, w1, b1, w2, b2);
    attn_kernel<<<dim3(S_ / BR, H_, BATCH_), NTHREAD, SMEM_BYTES>>>(O);
}